// round 15
// baseline (speedup 1.0000x reference)
#include <cuda_runtime.h>
#include <cuda_fp16.h>
#include <cstdint>
#include <math.h>

#define B_DIM 4096
#define IN_DIM 1024
#define H_DIM 1024
#define K_DIM 2048   // IN + H
#define N_DIM 4096   // 4*H, gate-interleaved: col n -> gate n&3, hidden n>>2

#define BM 128
#define BN 128
#define KC 64
#define NCHUNK (K_DIM / KC)     // 32

// SMEM tile rows: 64 fp16 = 128B data + 16B pad = 144B (conflict-free 16B-lane
// pattern for ldmatrix and cp.async).
#define ROWB 144
#define TILEB (128 * ROWB)            // 18432 B per matrix
#define OFF_A 0
#define OFF_W (TILEB)
#define BUFB  (2 * TILEB)             // 36864 B per stage
#define NSTAGE 3
#define SMEM_TOTAL (NSTAGE * BUFB)    // 110592 B

// Epilogue smem (reuses pipeline smem): 3 x [128][CPAD] fp32 = 55296 B
#define CPAD 36

// ---------------------------------------------------------------------------
// Device scratch
// ---------------------------------------------------------------------------
__device__ __half g_A[(size_t)B_DIM * K_DIM];
__device__ __half g_W[(size_t)N_DIM * K_DIM];
__device__ float g_biasp[N_DIM];

// ---------------------------------------------------------------------------
// PTX helpers (baseline PTX only: works on compute_103 virtual arch)
// ---------------------------------------------------------------------------
__device__ __forceinline__ uint32_t smem_u32(const void* p) {
    uint32_t a;
    asm("{ .reg .u64 t; cvta.to.shared.u64 t, %1; cvt.u32.u64 %0, t; }" : "=r"(a) : "l"(p));
    return a;
}
__device__ __forceinline__ void cp_async16(uint32_t dst, const void* src) {
    asm volatile("cp.async.cg.shared.global [%0], [%1], 16;" :: "r"(dst), "l"(src));
}
#define CP_COMMIT()  asm volatile("cp.async.commit_group;" ::: "memory")
#define CP_WAIT(N)   asm volatile("cp.async.wait_group %0;" :: "n"(N) : "memory")

__device__ __forceinline__ void ldsm4(uint32_t* r, uint32_t addr) {
    asm volatile("ldmatrix.sync.aligned.m8n8.x4.shared.b16 {%0,%1,%2,%3}, [%4];"
        : "=r"(r[0]), "=r"(r[1]), "=r"(r[2]), "=r"(r[3]) : "r"(addr));
}
__device__ __forceinline__ void mma16816(float* d, const uint32_t* a, const uint32_t* b) {
    asm volatile("mma.sync.aligned.m16n8k16.row.col.f32.f16.f16.f32 "
        "{%0,%1,%2,%3}, {%4,%5,%6,%7}, {%8,%9}, {%0,%1,%2,%3};"
        : "+f"(d[0]), "+f"(d[1]), "+f"(d[2]), "+f"(d[3])
        : "r"(a[0]), "r"(a[1]), "r"(a[2]), "r"(a[3]), "r"(b[0]), "r"(b[1]));
}

__device__ __forceinline__ float fast_sigmoid(float x) { return 1.0f / (1.0f + __expf(-x)); }
__device__ __forceinline__ float fast_tanh(float x) {
    float e = __expf(-2.0f * fabsf(x));
    return copysignf((1.0f - e) / (1.0f + e), x);
}

// ---------------------------------------------------------------------------
// Merged pack kernel:
//   blocks [0, 8192)          : A = [x | h] fp16          (B*K/4 float4s)
//   blocks [8192, 16384)      : W gate-interleaved fp16   (N*K/4 float4s)
//   blocks [16384, 16400)     : bias
// ---------------------------------------------------------------------------
#define PACK_A_BLKS 8192
#define PACK_W_BLKS 8192
#define PACK_B_BLKS 16
#define PACK_BLKS (PACK_A_BLKS + PACK_W_BLKS + PACK_B_BLKS)

__global__ void pack_all_kernel(
    const float4* __restrict__ x, const float4* __restrict__ h,
    const float4* __restrict__ Wxf, const float4* __restrict__ Wxi,
    const float4* __restrict__ Wxo, const float4* __restrict__ Wxc,
    const float4* __restrict__ Whf, const float4* __restrict__ Whi,
    const float4* __restrict__ Who, const float4* __restrict__ Whc,
    const float* __restrict__ bxf, const float* __restrict__ bxi,
    const float* __restrict__ bxo, const float* __restrict__ bxc,
    const float* __restrict__ bhf, const float* __restrict__ bhi,
    const float* __restrict__ bho, const float* __restrict__ bhc) {
    const int bid = blockIdx.x;
    if (bid < PACK_A_BLKS) {
        int i = bid * 256 + threadIdx.x;             // over B*K/4
        int b = i >> 9, k4 = i & 511;
        float4 v = (k4 < 256) ? x[b * 256 + k4] : h[b * 256 + (k4 - 256)];
        __half2* A2 = reinterpret_cast<__half2*>(g_A);
        A2[i * 2]     = __halves2half2(__float2half(v.x), __float2half(v.y));
        A2[i * 2 + 1] = __halves2half2(__float2half(v.z), __float2half(v.w));
    } else if (bid < PACK_A_BLKS + PACK_W_BLKS) {
        int i = (bid - PACK_A_BLKS) * 256 + threadIdx.x;   // over N*K/4
        int n = i >> 9, k4 = i & 511;
        int g = n & 3, j = n >> 2;
        const float4* Wx[4] = {Wxf, Wxi, Wxo, Wxc};
        const float4* Wh[4] = {Whf, Whi, Who, Whc};
        float4 v = (k4 < 256) ? Wx[g][j * 256 + k4] : Wh[g][j * 256 + (k4 - 256)];
        __half2* W2 = reinterpret_cast<__half2*>(g_W);
        W2[i * 2]     = __halves2half2(__float2half(v.x), __float2half(v.y));
        W2[i * 2 + 1] = __halves2half2(__float2half(v.z), __float2half(v.w));
    } else {
        int n = (bid - PACK_A_BLKS - PACK_W_BLKS) * 256 + threadIdx.x;
        int g = n & 3, j = n >> 2;
        const float* bx[4] = {bxf, bxi, bxo, bxc};
        const float* bh[4] = {bhf, bhi, bho, bhc};
        g_biasp[n] = bx[g][j] + bh[g][j];
    }
}

// ---------------------------------------------------------------------------
// HMMA GEMM + fused LSTM epilogue.
// 8 warps: warp grid 2(M) x 4(N); warp tile 64x32; mma m16n8k16 fp16.
// KC=64 chunks; 3-stage cp.async pipeline + 2-deep register fragment pipeline.
// NEW: the 6 ldmatrix of step h+1 are WOVEN between the 16 MMAs of step h at
// the instruction level, so the LDS and tensor pipes are co-issued inside
// every warp's stream instead of alternating in bursts.
// ---------------------------------------------------------------------------
__global__ void __launch_bounds__(256, 2)
lstm_gemm_kernel(const float* __restrict__ c_in, float* __restrict__ out) {
    extern __shared__ char smem[];
    const uint32_t sb = smem_u32(smem);
    const int tid  = threadIdx.x;
    const int lane = tid & 31;
    const int wid  = tid >> 5;
    const int wm   = wid >> 2;         // 0..1
    const int wn   = wid & 3;          // 0..3
    const int m0   = blockIdx.y * BM;
    const int n0   = blockIdx.x * BN;

    // ---- chunk loader: 8 x 16B cp.async per thread (A 4, W 4) ----
    auto load_chunk = [&](int t, int stg) {
        const uint32_t base = sb + stg * BUFB;
        const int kg = t * KC;
        #pragma unroll
        for (int q = 0; q < 4; q++) {
            const int op = tid + q * 256;
            const int r = op >> 3, s = op & 7;
            const uint32_t so = (uint32_t)(r * ROWB + s * 16);
            cp_async16(base + OFF_A + so, g_A + (size_t)(m0 + r) * K_DIM + kg + s * 8);
            cp_async16(base + OFF_W + so, g_W + (size_t)(n0 + r) * K_DIM + kg + s * 8);
        }
        CP_COMMIT();
    };

    float acc[4][4][4];
    #pragma unroll
    for (int i = 0; i < 4; i++)
        #pragma unroll
        for (int j = 0; j < 4; j++)
            #pragma unroll
            for (int e = 0; e < 4; e++) acc[i][j][e] = 0.0f;

    // Prologue: fill NSTAGE stages (0,1,2)
    load_chunk(0, 0);
    load_chunk(1, 1);
    load_chunk(2, 2);

    // Loop-invariant ldmatrix offsets
    const int a_row = lane & 15;
    const int a_col = (lane >> 4) * 16;
    const int b_row = (lane & 7) + (lane >> 4) * 8;
    const int b_col = ((lane >> 3) & 1) * 16;
    uint32_t aoff[4], woff[2];
    #pragma unroll
    for (int mi = 0; mi < 4; mi++)
        aoff[mi] = (uint32_t)((wm * 64 + mi * 16 + a_row) * ROWB + a_col) + OFF_A;
    #pragma unroll
    for (int f = 0; f < 2; f++)
        woff[f] = (uint32_t)((wn * 32 + f * 16 + b_row) * ROWB + b_col) + OFF_W;

    // Fragment double buffers
    uint32_t ah0[16], ah1[16], bb0[8], bb1[8];

    auto ld_frags = [&](uint32_t base, int h, uint32_t* ap, uint32_t* bp) {
        const uint32_t hb = base + (uint32_t)(h * 32);
        #pragma unroll
        for (int mi = 0; mi < 4; mi++) ldsm4(&ap[mi * 4], hb + aoff[mi]);
        #pragma unroll
        for (int f = 0; f < 2; f++)    ldsm4(&bp[f * 4], hb + woff[f]);
    };
    auto do_mmas = [&](const uint32_t* ap, const uint32_t* bp) {
        #pragma unroll
        for (int mi = 0; mi < 4; mi++)
            #pragma unroll
            for (int nj = 0; nj < 4; nj++)
                mma16816(acc[mi][nj], &ap[mi * 4], &bp[(nj >> 1) * 4 + (nj & 1) * 2]);
    };

    // Fused step: 16 MMAs of the CURRENT step (ap/bp) with the 6 ldmatrix of
    // the NEXT step (ap_n/bp_n from nb + hn*32) interleaved between them.
    auto step_fused = [&](uint32_t nb, int hn, uint32_t* ap_n, uint32_t* bp_n,
                          const uint32_t* ap, const uint32_t* bp) {
        const uint32_t hb = nb + (uint32_t)(hn * 32);
        ldsm4(&ap_n[0],  hb + aoff[0]);
        mma16816(acc[0][0], &ap[0],  &bp[0]);
        mma16816(acc[0][1], &ap[0],  &bp[2]);
        mma16816(acc[0][2], &ap[0],  &bp[4]);
        ldsm4(&ap_n[4],  hb + aoff[1]);
        mma16816(acc[0][3], &ap[0],  &bp[6]);
        mma16816(acc[1][0], &ap[4],  &bp[0]);
        mma16816(acc[1][1], &ap[4],  &bp[2]);
        ldsm4(&ap_n[8],  hb + aoff[2]);
        mma16816(acc[1][2], &ap[4],  &bp[4]);
        mma16816(acc[1][3], &ap[4],  &bp[6]);
        ldsm4(&ap_n[12], hb + aoff[3]);
        mma16816(acc[2][0], &ap[8],  &bp[0]);
        mma16816(acc[2][1], &ap[8],  &bp[2]);
        ldsm4(&bp_n[0],  hb + woff[0]);
        mma16816(acc[2][2], &ap[8],  &bp[4]);
        mma16816(acc[2][3], &ap[8],  &bp[6]);
        ldsm4(&bp_n[4],  hb + woff[1]);
        mma16816(acc[3][0], &ap[12], &bp[0]);
        mma16816(acc[3][1], &ap[12], &bp[2]);
        mma16816(acc[3][2], &ap[12], &bp[4]);
        mma16816(acc[3][3], &ap[12], &bp[6]);
    };

    // Steady-state invariant at loop top: chunk t visible, frags (t,0) in buf0.
    CP_WAIT(2);
    __syncthreads();
    ld_frags(sb, 0, ah0, bb0);

    int stg = 0;
    for (int t = 0; t < NCHUNK; t++) {
        const uint32_t base = sb + stg * BUFB;
        const int nstg = (stg == NSTAGE - 1) ? 0 : stg + 1;

        step_fused(base, 1, ah1, bb1, ah0, bb0);   // compute (t,0), load (t,1)
        step_fused(base, 2, ah0, bb0, ah1, bb1);   // compute (t,1), load (t,2)
        step_fused(base, 3, ah1, bb1, ah0, bb0);   // compute (t,2), load (t,3)

        // Own cp.async groups: leave <=1 pending -> chunk t+1 complete for all
        // threads, then barrier (also closes reads of stage stg for rewrite).
        if (t < NCHUNK - 2) CP_WAIT(1); else CP_WAIT(0);
        __syncthreads();

        if (t + 3 < NCHUNK) load_chunk(t + 3, stg);   // (t+3)%3 == t%3
        if (t + 1 < NCHUNK)
            step_fused(sb + nstg * BUFB, 0, ah0, bb0, ah1, bb1);  // (t,3)+(t+1,0)
        else
            do_mmas(ah1, bb1);                                    // (t,3) tail
        stg = nstg;
    }

    // ---- fused LSTM epilogue, coalesced via smem transpose ----
    // Block owns rows m0..m0+127, hidden units u0..u0+31.
    __syncthreads();   // all pipeline smem reads done; reuse smem
    float* s_c  = reinterpret_cast<float*>(smem);
    float* s_ct = s_c + 128 * CPAD;
    float* s_ht = s_c + 2 * 128 * CPAD;
    const int u0 = n0 >> 2;

    // Coalesced load of previous cell state tile (128 rows x 32 units)
    #pragma unroll
    for (int it = 0; it < 4; it++) {
        int i = tid + it * 256;               // over 128*8 float4 slots
        int row = i >> 3, uq = i & 7;
        float4 v = *reinterpret_cast<const float4*>(
            c_in + (size_t)(m0 + row) * H_DIM + u0 + uq * 4);
        *reinterpret_cast<float4*>(s_c + row * CPAD + uq * 4) = v;
    }
    __syncthreads();

    // D frag: d0,d1 = row (lane>>2), cols q*2,q*2+1 ; d2,d3 = row+8 (q = lane&3)
    // q even lane holds (f,i), odd (o,c); shfl-xor(1) completes each unit.
    const bool fi = ((lane & 1) == 0);
    const int q = lane & 3;

    #pragma unroll
    for (int nj = 0; nj < 4; nj++) {
        const int nb = n0 + wn * 32 + nj * 8 + q * 2;
        const float b0 = g_biasp[nb];
        const float b1 = g_biasp[nb + 1];
        const int ul = wn * 8 + nj * 2 + (q >> 1);   // local unit 0..31
        #pragma unroll
        for (int mi = 0; mi < 4; mi++) {
            const int rbase = wm * 64 + mi * 16 + (lane >> 2);
            float z0 = acc[mi][nj][0] + b0;
            float z1 = acc[mi][nj][1] + b1;
            float z2 = acc[mi][nj][2] + b0;
            float z3 = acc[mi][nj][3] + b1;
            float v0 = fast_sigmoid(z0);
            float v1 = fi ? fast_sigmoid(z1) : fast_tanh(z1);
            float v2 = fast_sigmoid(z2);
            float v3 = fi ? fast_sigmoid(z3) : fast_tanh(z3);
            float s0 = fi ? v2 : v0;
            float s1 = fi ? v3 : v1;
            float r0 = __shfl_xor_sync(0xffffffffu, s0, 1);
            float r1 = __shfl_xor_sync(0xffffffffu, s1, 1);
            const int row = rbase + (fi ? 0 : 8);
            float gf = fi ? v0 : r0;
            float gi = fi ? v1 : r1;
            float go = fi ? r0 : v2;
            float gc = fi ? r1 : v3;
            float cp = s_c[row * CPAD + ul];
            float ct = gf * cp + gc * gi;
            float ht = fast_tanh(ct) * go;
            s_ct[row * CPAD + ul] = ct;
            s_ht[row * CPAD + ul] = ht;
        }
    }
    __syncthreads();

    // Coalesced global writes
    float* ht_base = out + (size_t)B_DIM * H_DIM;
    #pragma unroll
    for (int it = 0; it < 4; it++) {
        int i = tid + it * 256;
        int row = i >> 3, uq = i & 7;
        *reinterpret_cast<float4*>(out + (size_t)(m0 + row) * H_DIM + u0 + uq * 4) =
            *reinterpret_cast<float4*>(s_ct + row * CPAD + uq * 4);
        *reinterpret_cast<float4*>(ht_base + (size_t)(m0 + row) * H_DIM + u0 + uq * 4) =
            *reinterpret_cast<float4*>(s_ht + row * CPAD + uq * 4);
    }
}

// ---------------------------------------------------------------------------
// kernel_launch
// Inputs: x, c, h, Wxf, bxf, Whf, bhf, Wxi, bxi, Whi, bhi,
//         Wxo, bxo, Who, bho, Wxc, bxc, Whc, bhc
// ---------------------------------------------------------------------------
extern "C" void kernel_launch(void* const* d_in, const int* in_sizes, int n_in,
                              void* d_out, int out_size) {
    const float* x   = (const float*)d_in[0];
    const float* c   = (const float*)d_in[1];
    const float* h   = (const float*)d_in[2];
    const float* Wxf = (const float*)d_in[3];
    const float* bxf = (const float*)d_in[4];
    const float* Whf = (const float*)d_in[5];
    const float* bhf = (const float*)d_in[6];
    const float* Wxi = (const float*)d_in[7];
    const float* bxi = (const float*)d_in[8];
    const float* Whi = (const float*)d_in[9];
    const float* bhi = (const float*)d_in[10];
    const float* Wxo = (const float*)d_in[11];
    const float* bxo = (const float*)d_in[12];
    const float* Who = (const float*)d_in[13];
    const float* bho = (const float*)d_in[14];
    const float* Wxc = (const float*)d_in[15];
    const float* bxc = (const float*)d_in[16];
    const float* Whc = (const float*)d_in[17];
    const float* bhc = (const float*)d_in[18];

    pack_all_kernel<<<PACK_BLKS, 256>>>(
        (const float4*)x, (const float4*)h,
        (const float4*)Wxf, (const float4*)Wxi, (const float4*)Wxo, (const float4*)Wxc,
        (const float4*)Whf, (const float4*)Whi, (const float4*)Who, (const float4*)Whc,
        bxf, bxi, bxo, bxc, bhf, bhi, bho, bhc);

    cudaFuncSetAttribute(lstm_gemm_kernel,
                         cudaFuncAttributeMaxDynamicSharedMemorySize, SMEM_TOTAL);
    dim3 grid(N_DIM / BN, B_DIM / BM);   // (32, 32)
    lstm_gemm_kernel<<<grid, 256, SMEM_TOTAL>>>(c, (float*)d_out);
}

// round 16
// speedup vs baseline: 3.6207x; 3.6207x over previous
#include <cuda_runtime.h>
#include <cuda_fp16.h>
#include <cstdint>
#include <math.h>

#define B_DIM 4096
#define IN_DIM 1024
#define H_DIM 1024
#define K_DIM 2048   // IN + H
#define N_DIM 4096   // 4*H, gate-interleaved: col n -> gate n&3, hidden n>>2

#define BM 128
#define BN 128
#define KC 64
#define NCHUNK (K_DIM / KC)     // 32

// SMEM tile rows: 64 fp16 = 128B data + 16B pad = 144B (conflict-free 16B-lane
// pattern for ldmatrix and cp.async).
#define ROWB 144
#define TILEB (128 * ROWB)            // 18432 B per matrix
#define OFF_A 0
#define OFF_W (TILEB)
#define BUFB  (2 * TILEB)             // 36864 B per stage
#define NSTAGE 3
#define SMEM_TOTAL (NSTAGE * BUFB)    // 110592 B

// Epilogue smem (reuses pipeline smem): 3 x [128][CPAD] fp32 = 55296 B
// CPAD*4 = 144 = ROWB, so the c-tile cp.async prefetch into stage 0's A
// region lands exactly on s_c's layout.
#define CPAD 36

// ---------------------------------------------------------------------------
// Device scratch
// ---------------------------------------------------------------------------
__device__ __half g_A[(size_t)B_DIM * K_DIM];
__device__ __half g_W[(size_t)N_DIM * K_DIM];
__device__ float g_biasp[N_DIM];

// ---------------------------------------------------------------------------
// PTX helpers (baseline PTX only: works on compute_103 virtual arch)
// ---------------------------------------------------------------------------
__device__ __forceinline__ uint32_t smem_u32(const void* p) {
    uint32_t a;
    asm("{ .reg .u64 t; cvta.to.shared.u64 t, %1; cvt.u32.u64 %0, t; }" : "=r"(a) : "l"(p));
    return a;
}
__device__ __forceinline__ void cp_async16(uint32_t dst, const void* src) {
    asm volatile("cp.async.cg.shared.global [%0], [%1], 16;" :: "r"(dst), "l"(src));
}
#define CP_COMMIT()  asm volatile("cp.async.commit_group;" ::: "memory")
#define CP_WAIT(N)   asm volatile("cp.async.wait_group %0;" :: "n"(N) : "memory")

__device__ __forceinline__ void ldsm4(uint32_t* r, uint32_t addr) {
    asm volatile("ldmatrix.sync.aligned.m8n8.x4.shared.b16 {%0,%1,%2,%3}, [%4];"
        : "=r"(r[0]), "=r"(r[1]), "=r"(r[2]), "=r"(r[3]) : "r"(addr));
}
__device__ __forceinline__ void mma16816(float* d, const uint32_t* a, const uint32_t* b) {
    asm volatile("mma.sync.aligned.m16n8k16.row.col.f32.f16.f16.f32 "
        "{%0,%1,%2,%3}, {%4,%5,%6,%7}, {%8,%9}, {%0,%1,%2,%3};"
        : "+f"(d[0]), "+f"(d[1]), "+f"(d[2]), "+f"(d[3])
        : "r"(a[0]), "r"(a[1]), "r"(a[2]), "r"(a[3]), "r"(b[0]), "r"(b[1]));
}

__device__ __forceinline__ float fast_sigmoid(float x) { return 1.0f / (1.0f + __expf(-x)); }
__device__ __forceinline__ float fast_tanh(float x) {
    float e = __expf(-2.0f * fabsf(x));
    return copysignf((1.0f - e) / (1.0f + e), x);
}

// ---------------------------------------------------------------------------
// Merged pack kernel (read-once inputs via __ldcs to preserve L2 for outputs):
//   blocks [0, 8192)          : A = [x | h] fp16          (B*K/4 float4s)
//   blocks [8192, 16384)      : W gate-interleaved fp16   (N*K/4 float4s)
//   blocks [16384, 16400)     : bias
// ---------------------------------------------------------------------------
#define PACK_A_BLKS 8192
#define PACK_W_BLKS 8192
#define PACK_B_BLKS 16
#define PACK_BLKS (PACK_A_BLKS + PACK_W_BLKS + PACK_B_BLKS)

__global__ void pack_all_kernel(
    const float4* __restrict__ x, const float4* __restrict__ h,
    const float4* __restrict__ Wxf, const float4* __restrict__ Wxi,
    const float4* __restrict__ Wxo, const float4* __restrict__ Wxc,
    const float4* __restrict__ Whf, const float4* __restrict__ Whi,
    const float4* __restrict__ Who, const float4* __restrict__ Whc,
    const float* __restrict__ bxf, const float* __restrict__ bxi,
    const float* __restrict__ bxo, const float* __restrict__ bxc,
    const float* __restrict__ bhf, const float* __restrict__ bhi,
    const float* __restrict__ bho, const float* __restrict__ bhc) {
    const int bid = blockIdx.x;
    if (bid < PACK_A_BLKS) {
        int i = bid * 256 + threadIdx.x;             // over B*K/4
        int b = i >> 9, k4 = i & 511;
        float4 v = (k4 < 256) ? __ldcs(&x[b * 256 + k4]) : __ldcs(&h[b * 256 + (k4 - 256)]);
        __half2* A2 = reinterpret_cast<__half2*>(g_A);
        A2[i * 2]     = __halves2half2(__float2half(v.x), __float2half(v.y));
        A2[i * 2 + 1] = __halves2half2(__float2half(v.z), __float2half(v.w));
    } else if (bid < PACK_A_BLKS + PACK_W_BLKS) {
        int i = (bid - PACK_A_BLKS) * 256 + threadIdx.x;   // over N*K/4
        int n = i >> 9, k4 = i & 511;
        int g = n & 3, j = n >> 2;
        const float4* Wx[4] = {Wxf, Wxi, Wxo, Wxc};
        const float4* Wh[4] = {Whf, Whi, Who, Whc};
        float4 v = (k4 < 256) ? __ldcs(&Wx[g][j * 256 + k4])
                              : __ldcs(&Wh[g][j * 256 + (k4 - 256)]);
        __half2* W2 = reinterpret_cast<__half2*>(g_W);
        W2[i * 2]     = __halves2half2(__float2half(v.x), __float2half(v.y));
        W2[i * 2 + 1] = __halves2half2(__float2half(v.z), __float2half(v.w));
    } else {
        int n = (bid - PACK_A_BLKS - PACK_W_BLKS) * 256 + threadIdx.x;
        int g = n & 3, j = n >> 2;
        const float* bx[4] = {bxf, bxi, bxo, bxc};
        const float* bh[4] = {bhf, bhi, bho, bhc};
        g_biasp[n] = bx[g][j] + bh[g][j];
    }
}

// ---------------------------------------------------------------------------
// HMMA GEMM + fused LSTM epilogue.
// 8 warps: warp grid 2(M) x 4(N); warp tile 64x32; mma m16n8k16 fp16.
// KC=64 chunks; 3-stage cp.async pipeline + 2-deep register fragment pipeline.
// The previous-cell-state tile is prefetched via cp.async into the freed
// stage-0 region during the final chunk; outputs use streaming stores.
// ---------------------------------------------------------------------------
__global__ void __launch_bounds__(256, 2)
lstm_gemm_kernel(const float* __restrict__ c_in, float* __restrict__ out) {
    extern __shared__ char smem[];
    const uint32_t sb = smem_u32(smem);
    const int tid  = threadIdx.x;
    const int lane = tid & 31;
    const int wid  = tid >> 5;
    const int wm   = wid >> 2;         // 0..1
    const int wn   = wid & 3;          // 0..3
    const int m0   = blockIdx.y * BM;
    const int n0   = blockIdx.x * BN;
    const int u0   = n0 >> 2;

    // ---- chunk loader: 8 x 16B cp.async per thread (A 4, W 4) ----
    auto load_chunk = [&](int t, int stg) {
        const uint32_t base = sb + stg * BUFB;
        const int kg = t * KC;
        #pragma unroll
        for (int q = 0; q < 4; q++) {
            const int op = tid + q * 256;
            const int r = op >> 3, s = op & 7;
            const uint32_t so = (uint32_t)(r * ROWB + s * 16);
            cp_async16(base + OFF_A + so, g_A + (size_t)(m0 + r) * K_DIM + kg + s * 8);
            cp_async16(base + OFF_W + so, g_W + (size_t)(n0 + r) * K_DIM + kg + s * 8);
        }
        CP_COMMIT();
    };

    float acc[4][4][4];
    #pragma unroll
    for (int i = 0; i < 4; i++)
        #pragma unroll
        for (int j = 0; j < 4; j++)
            #pragma unroll
            for (int e = 0; e < 4; e++) acc[i][j][e] = 0.0f;

    // Prologue: fill NSTAGE stages (0,1,2)
    load_chunk(0, 0);
    load_chunk(1, 1);
    load_chunk(2, 2);

    // Loop-invariant ldmatrix offsets
    const int a_row = lane & 15;
    const int a_col = (lane >> 4) * 16;
    const int b_row = (lane & 7) + (lane >> 4) * 8;
    const int b_col = ((lane >> 3) & 1) * 16;
    uint32_t aoff[4], woff[2];
    #pragma unroll
    for (int mi = 0; mi < 4; mi++)
        aoff[mi] = (uint32_t)((wm * 64 + mi * 16 + a_row) * ROWB + a_col) + OFF_A;
    #pragma unroll
    for (int f = 0; f < 2; f++)
        woff[f] = (uint32_t)((wn * 32 + f * 16 + b_row) * ROWB + b_col) + OFF_W;

    // Fragment double buffers
    uint32_t ah0[16], ah1[16], bb0[8], bb1[8];

    auto ld_frags = [&](uint32_t base, int hs, uint32_t* ap, uint32_t* bp) {
        const uint32_t hb = base + (uint32_t)(hs * 32);
        #pragma unroll
        for (int mi = 0; mi < 4; mi++) ldsm4(&ap[mi * 4], hb + aoff[mi]);
        #pragma unroll
        for (int f = 0; f < 2; f++)    ldsm4(&bp[f * 4], hb + woff[f]);
    };
    auto do_mmas = [&](const uint32_t* ap, const uint32_t* bp) {
        #pragma unroll
        for (int mi = 0; mi < 4; mi++)
            #pragma unroll
            for (int nj = 0; nj < 4; nj++)
                mma16816(acc[mi][nj], &ap[mi * 4], &bp[(nj >> 1) * 4 + (nj & 1) * 2]);
    };

    // Steady-state invariant at loop top: chunk t visible, frags (t,0) in buf0.
    CP_WAIT(2);
    __syncthreads();
    ld_frags(sb, 0, ah0, bb0);

    int stg = 0;
    for (int t = 0; t < NCHUNK; t++) {
        const uint32_t base = sb + stg * BUFB;
        const int nstg = (stg == NSTAGE - 1) ? 0 : stg + 1;

        ld_frags(base, 1, ah1, bb1);  do_mmas(ah0, bb0);   // (t,0)
        ld_frags(base, 2, ah0, bb0);  do_mmas(ah1, bb1);   // (t,1)
        ld_frags(base, 3, ah1, bb1);  do_mmas(ah0, bb0);   // (t,2)

        // Own cp.async groups: leave <=1 pending -> chunk t+1 complete for all
        // threads, then barrier (also closes reads of stage stg for rewrite).
        if (t < NCHUNK - 2) CP_WAIT(1); else CP_WAIT(0);
        __syncthreads();

        if (t + 3 < NCHUNK) {
            load_chunk(t + 3, stg);   // (t+3)%3 == t%3
        } else if (t == NCHUNK - 1) {
            // Final chunk: stage 0's reads finished at t=30 -> prefetch the
            // previous-cell-state tile into stage 0's A region, which is
            // exactly where the epilogue's s_c lives (CPAD*4 == ROWB).
            #pragma unroll
            for (int q = 0; q < 4; q++) {
                const int op = tid + q * 256;
                const int r = op >> 3, s = op & 7;
                cp_async16(sb + (uint32_t)(r * ROWB + s * 16),
                           c_in + (size_t)(m0 + r) * H_DIM + u0 + s * 4);
            }
            CP_COMMIT();
        }
        if (t + 1 < NCHUNK) ld_frags(sb + nstg * BUFB, 0, ah0, bb0);
        do_mmas(ah1, bb1);                                  // (t,3)
        stg = nstg;
    }

    // ---- fused LSTM epilogue, coalesced via smem transpose ----
    // Block owns rows m0..m0+127, hidden units u0..u0+31. s_c already loaded.
    CP_WAIT(0);
    __syncthreads();   // c tile visible; all pipeline smem reads done
    float* s_c  = reinterpret_cast<float*>(smem);
    float* s_ct = s_c + 128 * CPAD;
    float* s_ht = s_c + 2 * 128 * CPAD;

    // D frag: d0,d1 = row (lane>>2), cols q*2,q*2+1 ; d2,d3 = row+8 (q = lane&3)
    // q even lane holds (f,i), odd (o,c); shfl-xor(1) completes each unit.
    const bool fi = ((lane & 1) == 0);
    const int q = lane & 3;

    #pragma unroll
    for (int nj = 0; nj < 4; nj++) {
        const int nb = n0 + wn * 32 + nj * 8 + q * 2;
        const float b0 = g_biasp[nb];
        const float b1 = g_biasp[nb + 1];
        const int ul = wn * 8 + nj * 2 + (q >> 1);   // local unit 0..31
        #pragma unroll
        for (int mi = 0; mi < 4; mi++) {
            const int rbase = wm * 64 + mi * 16 + (lane >> 2);
            float z0 = acc[mi][nj][0] + b0;
            float z1 = acc[mi][nj][1] + b1;
            float z2 = acc[mi][nj][2] + b0;
            float z3 = acc[mi][nj][3] + b1;
            float v0 = fast_sigmoid(z0);
            float v1 = fi ? fast_sigmoid(z1) : fast_tanh(z1);
            float v2 = fast_sigmoid(z2);
            float v3 = fi ? fast_sigmoid(z3) : fast_tanh(z3);
            float s0 = fi ? v2 : v0;
            float s1 = fi ? v3 : v1;
            float r0 = __shfl_xor_sync(0xffffffffu, s0, 1);
            float r1 = __shfl_xor_sync(0xffffffffu, s1, 1);
            const int row = rbase + (fi ? 0 : 8);
            float gf = fi ? v0 : r0;
            float gi = fi ? v1 : r1;
            float go = fi ? r0 : v2;
            float gc = fi ? r1 : v3;
            float cp = s_c[row * CPAD + ul];
            float ct = gf * cp + gc * gi;
            float ht = fast_tanh(ct) * go;
            s_ct[row * CPAD + ul] = ct;
            s_ht[row * CPAD + ul] = ht;
        }
    }
    __syncthreads();

    // Coalesced streaming global writes (outputs are never re-read)
    float* ht_base = out + (size_t)B_DIM * H_DIM;
    #pragma unroll
    for (int it = 0; it < 4; it++) {
        int i = tid + it * 256;
        int row = i >> 3, uq = i & 7;
        float4 vct = *reinterpret_cast<float4*>(s_ct + row * CPAD + uq * 4);
        float4 vht = *reinterpret_cast<float4*>(s_ht + row * CPAD + uq * 4);
        __stcs(reinterpret_cast<float4*>(out + (size_t)(m0 + row) * H_DIM + u0 + uq * 4), vct);
        __stcs(reinterpret_cast<float4*>(ht_base + (size_t)(m0 + row) * H_DIM + u0 + uq * 4), vht);
    }
}

// ---------------------------------------------------------------------------
// kernel_launch
// Inputs: x, c, h, Wxf, bxf, Whf, bhf, Wxi, bxi, Whi, bhi,
//         Wxo, bxo, Who, bho, Wxc, bxc, Whc, bhc
// ---------------------------------------------------------------------------
extern "C" void kernel_launch(void* const* d_in, const int* in_sizes, int n_in,
                              void* d_out, int out_size) {
    const float* x   = (const float*)d_in[0];
    const float* c   = (const float*)d_in[1];
    const float* h   = (const float*)d_in[2];
    const float* Wxf = (const float*)d_in[3];
    const float* bxf = (const float*)d_in[4];
    const float* Whf = (const float*)d_in[5];
    const float* bhf = (const float*)d_in[6];
    const float* Wxi = (const float*)d_in[7];
    const float* bxi = (const float*)d_in[8];
    const float* Whi = (const float*)d_in[9];
    const float* bhi = (const float*)d_in[10];
    const float* Wxo = (const float*)d_in[11];
    const float* bxo = (const float*)d_in[12];
    const float* Who = (const float*)d_in[13];
    const float* bho = (const float*)d_in[14];
    const float* Wxc = (const float*)d_in[15];
    const float* bxc = (const float*)d_in[16];
    const float* Whc = (const float*)d_in[17];
    const float* bhc = (const float*)d_in[18];

    pack_all_kernel<<<PACK_BLKS, 256>>>(
        (const float4*)x, (const float4*)h,
        (const float4*)Wxf, (const float4*)Wxi, (const float4*)Wxo, (const float4*)Wxc,
        (const float4*)Whf, (const float4*)Whi, (const float4*)Who, (const float4*)Whc,
        bxf, bxi, bxo, bxc, bhf, bhi, bho, bhc);

    cudaFuncSetAttribute(lstm_gemm_kernel,
                         cudaFuncAttributeMaxDynamicSharedMemorySize, SMEM_TOTAL);
    dim3 grid(N_DIM / BN, B_DIM / BM);   // (32, 32)
    lstm_gemm_kernel<<<grid, 256, SMEM_TOTAL>>>(c, (float*)d_out);
}

// round 17
// speedup vs baseline: 3.7390x; 1.0327x over previous
#include <cuda_runtime.h>
#include <cuda_fp16.h>
#include <cstdint>
#include <math.h>

#define B_DIM 4096
#define IN_DIM 1024
#define H_DIM 1024
#define K_DIM 2048   // IN + H
#define N_DIM 4096   // 4*H, gate-interleaved: col n -> gate n&3, hidden n>>2

#define BM 128
#define BN 128
#define KC 64
#define NCHUNK (K_DIM / KC)     // 32

// SMEM tile rows: 64 fp16 = 128B data + 16B pad = 144B (conflict-free 16B-lane
// pattern for ldmatrix and cp.async).
#define ROWB 144
#define TILEB (128 * ROWB)            // 18432 B per matrix
#define OFF_A 0
#define OFF_W (TILEB)
#define BUFB  (2 * TILEB)             // 36864 B per stage
#define NSTAGE 3
#define SMEM_TOTAL (NSTAGE * BUFB)    // 110592 B

// Epilogue smem (reuses pipeline smem): 3 x [128][CPAD] fp32 = 55296 B
#define CPAD 36

// ---------------------------------------------------------------------------
// Device scratch
// ---------------------------------------------------------------------------
__device__ __half g_A[(size_t)B_DIM * K_DIM];
__device__ __half g_W[(size_t)N_DIM * K_DIM];
__device__ float g_biasp[N_DIM];

// ---------------------------------------------------------------------------
// PTX helpers (baseline PTX only: works on compute_103 virtual arch)
// ---------------------------------------------------------------------------
__device__ __forceinline__ uint32_t smem_u32(const void* p) {
    uint32_t a;
    asm("{ .reg .u64 t; cvta.to.shared.u64 t, %1; cvt.u32.u64 %0, t; }" : "=r"(a) : "l"(p));
    return a;
}
__device__ __forceinline__ void cp_async16(uint32_t dst, const void* src) {
    asm volatile("cp.async.cg.shared.global [%0], [%1], 16;" :: "r"(dst), "l"(src));
}
#define CP_COMMIT()  asm volatile("cp.async.commit_group;" ::: "memory")
#define CP_WAIT(N)   asm volatile("cp.async.wait_group %0;" :: "n"(N) : "memory")

__device__ __forceinline__ void ldsm4(uint32_t* r, uint32_t addr) {
    asm volatile("ldmatrix.sync.aligned.m8n8.x4.shared.b16 {%0,%1,%2,%3}, [%4];"
        : "=r"(r[0]), "=r"(r[1]), "=r"(r[2]), "=r"(r[3]) : "r"(addr));
}
__device__ __forceinline__ void mma16816(float* d, const uint32_t* a, const uint32_t* b) {
    asm volatile("mma.sync.aligned.m16n8k16.row.col.f32.f16.f16.f32 "
        "{%0,%1,%2,%3}, {%4,%5,%6,%7}, {%8,%9}, {%0,%1,%2,%3};"
        : "+f"(d[0]), "+f"(d[1]), "+f"(d[2]), "+f"(d[3])
        : "r"(a[0]), "r"(a[1]), "r"(a[2]), "r"(a[3]), "r"(b[0]), "r"(b[1]));
}

__device__ __forceinline__ float fast_sigmoid(float x) { return 1.0f / (1.0f + __expf(-x)); }
__device__ __forceinline__ float fast_tanh(float x) {
    float e = __expf(-2.0f * fabsf(x));
    return copysignf((1.0f - e) / (1.0f + e), x);
}

// ---------------------------------------------------------------------------
// Merged pack kernel (read-once inputs via __ldcs to preserve L2 for outputs):
//   blocks [0, 8192)          : A = [x | h] fp16          (B*K/4 float4s)
//   blocks [8192, 16384)      : W gate-interleaved fp16   (N*K/4 float4s)
//   blocks [16384, 16400)     : bias
// ---------------------------------------------------------------------------
#define PACK_A_BLKS 8192
#define PACK_W_BLKS 8192
#define PACK_B_BLKS 16
#define PACK_BLKS (PACK_A_BLKS + PACK_W_BLKS + PACK_B_BLKS)

__global__ void pack_all_kernel(
    const float4* __restrict__ x, const float4* __restrict__ h,
    const float4* __restrict__ Wxf, const float4* __restrict__ Wxi,
    const float4* __restrict__ Wxo, const float4* __restrict__ Wxc,
    const float4* __restrict__ Whf, const float4* __restrict__ Whi,
    const float4* __restrict__ Who, const float4* __restrict__ Whc,
    const float* __restrict__ bxf, const float* __restrict__ bxi,
    const float* __restrict__ bxo, const float* __restrict__ bxc,
    const float* __restrict__ bhf, const float* __restrict__ bhi,
    const float* __restrict__ bho, const float* __restrict__ bhc) {
    const int bid = blockIdx.x;
    if (bid < PACK_A_BLKS) {
        int i = bid * 256 + threadIdx.x;             // over B*K/4
        int b = i >> 9, k4 = i & 511;
        float4 v = (k4 < 256) ? __ldcs(&x[b * 256 + k4]) : __ldcs(&h[b * 256 + (k4 - 256)]);
        __half2* A2 = reinterpret_cast<__half2*>(g_A);
        A2[i * 2]     = __halves2half2(__float2half(v.x), __float2half(v.y));
        A2[i * 2 + 1] = __halves2half2(__float2half(v.z), __float2half(v.w));
    } else if (bid < PACK_A_BLKS + PACK_W_BLKS) {
        int i = (bid - PACK_A_BLKS) * 256 + threadIdx.x;   // over N*K/4
        int n = i >> 9, k4 = i & 511;
        int g = n & 3, j = n >> 2;
        const float4* Wx[4] = {Wxf, Wxi, Wxo, Wxc};
        const float4* Wh[4] = {Whf, Whi, Who, Whc};
        float4 v = (k4 < 256) ? __ldcs(&Wx[g][j * 256 + k4])
                              : __ldcs(&Wh[g][j * 256 + (k4 - 256)]);
        __half2* W2 = reinterpret_cast<__half2*>(g_W);
        W2[i * 2]     = __halves2half2(__float2half(v.x), __float2half(v.y));
        W2[i * 2 + 1] = __halves2half2(__float2half(v.z), __float2half(v.w));
    } else {
        int n = (bid - PACK_A_BLKS - PACK_W_BLKS) * 256 + threadIdx.x;
        int g = n & 3, j = n >> 2;
        const float* bx[4] = {bxf, bxi, bxo, bxc};
        const float* bh[4] = {bhf, bhi, bho, bhc};
        g_biasp[n] = bx[g][j] + bh[g][j];
    }
}

// ---------------------------------------------------------------------------
// HMMA GEMM + fused LSTM epilogue.
// 8 warps: warp grid 2(M) x 4(N); warp tile 64x32; mma m16n8k16 fp16.
// KC=64 chunks; 3-stage cp.async pipeline + 2-deep register fragment pipeline.
// Mainloop identical to the proven 205us schedule; epilogue uses streaming
// stores (post-loop only).
// ---------------------------------------------------------------------------
__global__ void __launch_bounds__(256, 2)
lstm_gemm_kernel(const float* __restrict__ c_in, float* __restrict__ out) {
    extern __shared__ char smem[];
    const uint32_t sb = smem_u32(smem);
    const int tid  = threadIdx.x;
    const int lane = tid & 31;
    const int wid  = tid >> 5;
    const int wm   = wid >> 2;         // 0..1
    const int wn   = wid & 3;          // 0..3
    const int m0   = blockIdx.y * BM;
    const int n0   = blockIdx.x * BN;

    // ---- chunk loader: 8 x 16B cp.async per thread (A 4, W 4) ----
    auto load_chunk = [&](int t, int stg) {
        const uint32_t base = sb + stg * BUFB;
        const int kg = t * KC;
        #pragma unroll
        for (int q = 0; q < 4; q++) {
            const int op = tid + q * 256;
            const int r = op >> 3, s = op & 7;
            const uint32_t so = (uint32_t)(r * ROWB + s * 16);
            cp_async16(base + OFF_A + so, g_A + (size_t)(m0 + r) * K_DIM + kg + s * 8);
            cp_async16(base + OFF_W + so, g_W + (size_t)(n0 + r) * K_DIM + kg + s * 8);
        }
        CP_COMMIT();
    };

    float acc[4][4][4];
    #pragma unroll
    for (int i = 0; i < 4; i++)
        #pragma unroll
        for (int j = 0; j < 4; j++)
            #pragma unroll
            for (int e = 0; e < 4; e++) acc[i][j][e] = 0.0f;

    // Prologue: fill NSTAGE stages (0,1,2)
    load_chunk(0, 0);
    load_chunk(1, 1);
    load_chunk(2, 2);

    // Loop-invariant ldmatrix offsets
    const int a_row = lane & 15;
    const int a_col = (lane >> 4) * 16;
    const int b_row = (lane & 7) + (lane >> 4) * 8;
    const int b_col = ((lane >> 3) & 1) * 16;
    uint32_t aoff[4], woff[2];
    #pragma unroll
    for (int mi = 0; mi < 4; mi++)
        aoff[mi] = (uint32_t)((wm * 64 + mi * 16 + a_row) * ROWB + a_col) + OFF_A;
    #pragma unroll
    for (int f = 0; f < 2; f++)
        woff[f] = (uint32_t)((wn * 32 + f * 16 + b_row) * ROWB + b_col) + OFF_W;

    // Fragment double buffers
    uint32_t ah0[16], ah1[16], bb0[8], bb1[8];

    auto ld_frags = [&](uint32_t base, int hs, uint32_t* ap, uint32_t* bp) {
        const uint32_t hb = base + (uint32_t)(hs * 32);
        #pragma unroll
        for (int mi = 0; mi < 4; mi++) ldsm4(&ap[mi * 4], hb + aoff[mi]);
        #pragma unroll
        for (int f = 0; f < 2; f++)    ldsm4(&bp[f * 4], hb + woff[f]);
    };
    auto do_mmas = [&](const uint32_t* ap, const uint32_t* bp) {
        #pragma unroll
        for (int mi = 0; mi < 4; mi++)
            #pragma unroll
            for (int nj = 0; nj < 4; nj++)
                mma16816(acc[mi][nj], &ap[mi * 4], &bp[(nj >> 1) * 4 + (nj & 1) * 2]);
    };

    // Steady-state invariant at loop top: chunk t visible, frags (t,0) in buf0.
    CP_WAIT(2);
    __syncthreads();
    ld_frags(sb, 0, ah0, bb0);

    int stg = 0;
    for (int t = 0; t < NCHUNK; t++) {
        const uint32_t base = sb + stg * BUFB;
        const int nstg = (stg == NSTAGE - 1) ? 0 : stg + 1;

        ld_frags(base, 1, ah1, bb1);  do_mmas(ah0, bb0);   // (t,0)
        ld_frags(base, 2, ah0, bb0);  do_mmas(ah1, bb1);   // (t,1)
        ld_frags(base, 3, ah1, bb1);  do_mmas(ah0, bb0);   // (t,2)

        // Own cp.async groups: leave <=1 pending -> chunk t+1 complete for all
        // threads, then barrier (also closes reads of stage stg for rewrite).
        if (t < NCHUNK - 2) CP_WAIT(1); else CP_WAIT(0);
        __syncthreads();

        if (t + 3 < NCHUNK) load_chunk(t + 3, stg);   // (t+3)%3 == t%3
        if (t + 1 < NCHUNK) ld_frags(sb + nstg * BUFB, 0, ah0, bb0);
        do_mmas(ah1, bb1);                                  // (t,3)
        stg = nstg;
    }

    // ---- fused LSTM epilogue, coalesced via smem transpose ----
    // Block owns rows m0..m0+127, hidden units u0..u0+31.
    __syncthreads();   // all pipeline smem reads done; reuse smem
    float* s_c  = reinterpret_cast<float*>(smem);
    float* s_ct = s_c + 128 * CPAD;
    float* s_ht = s_c + 2 * 128 * CPAD;
    const int u0 = n0 >> 2;

    // Coalesced load of previous cell state tile (128 rows x 32 units)
    #pragma unroll
    for (int it = 0; it < 4; it++) {
        int i = tid + it * 256;               // over 128*8 float4 slots
        int row = i >> 3, uq = i & 7;
        float4 v = *reinterpret_cast<const float4*>(
            c_in + (size_t)(m0 + row) * H_DIM + u0 + uq * 4);
        *reinterpret_cast<float4*>(s_c + row * CPAD + uq * 4) = v;
    }
    __syncthreads();

    // D frag: d0,d1 = row (lane>>2), cols q*2,q*2+1 ; d2,d3 = row+8 (q = lane&3)
    // q even lane holds (f,i), odd (o,c); shfl-xor(1) completes each unit.
    const bool fi = ((lane & 1) == 0);
    const int q = lane & 3;

    #pragma unroll
    for (int nj = 0; nj < 4; nj++) {
        const int nb = n0 + wn * 32 + nj * 8 + q * 2;
        const float b0 = g_biasp[nb];
        const float b1 = g_biasp[nb + 1];
        const int ul = wn * 8 + nj * 2 + (q >> 1);   // local unit 0..31
        #pragma unroll
        for (int mi = 0; mi < 4; mi++) {
            const int rbase = wm * 64 + mi * 16 + (lane >> 2);
            float z0 = acc[mi][nj][0] + b0;
            float z1 = acc[mi][nj][1] + b1;
            float z2 = acc[mi][nj][2] + b0;
            float z3 = acc[mi][nj][3] + b1;
            float v0 = fast_sigmoid(z0);
            float v1 = fi ? fast_sigmoid(z1) : fast_tanh(z1);
            float v2 = fast_sigmoid(z2);
            float v3 = fi ? fast_sigmoid(z3) : fast_tanh(z3);
            float s0 = fi ? v2 : v0;
            float s1 = fi ? v3 : v1;
            float r0 = __shfl_xor_sync(0xffffffffu, s0, 1);
            float r1 = __shfl_xor_sync(0xffffffffu, s1, 1);
            const int row = rbase + (fi ? 0 : 8);
            float gf = fi ? v0 : r0;
            float gi = fi ? v1 : r1;
            float go = fi ? r0 : v2;
            float gc = fi ? r1 : v3;
            float cp = s_c[row * CPAD + ul];
            float ct = gf * cp + gc * gi;
            float ht = fast_tanh(ct) * go;
            s_ct[row * CPAD + ul] = ct;
            s_ht[row * CPAD + ul] = ht;
        }
    }
    __syncthreads();

    // Coalesced streaming global writes (outputs are never re-read)
    float* ht_base = out + (size_t)B_DIM * H_DIM;
    #pragma unroll
    for (int it = 0; it < 4; it++) {
        int i = tid + it * 256;
        int row = i >> 3, uq = i & 7;
        float4 vct = *reinterpret_cast<float4*>(s_ct + row * CPAD + uq * 4);
        float4 vht = *reinterpret_cast<float4*>(s_ht + row * CPAD + uq * 4);
        __stcs(reinterpret_cast<float4*>(out + (size_t)(m0 + row) * H_DIM + u0 + uq * 4), vct);
        __stcs(reinterpret_cast<float4*>(ht_base + (size_t)(m0 + row) * H_DIM + u0 + uq * 4), vht);
    }
}

// ---------------------------------------------------------------------------
// kernel_launch
// Inputs: x, c, h, Wxf, bxf, Whf, bhf, Wxi, bxi, Whi, bhi,
//         Wxo, bxo, Who, bho, Wxc, bxc, Whc, bhc
// ---------------------------------------------------------------------------
extern "C" void kernel_launch(void* const* d_in, const int* in_sizes, int n_in,
                              void* d_out, int out_size) {
    const float* x   = (const float*)d_in[0];
    const float* c   = (const float*)d_in[1];
    const float* h   = (const float*)d_in[2];
    const float* Wxf = (const float*)d_in[3];
    const float* bxf = (const float*)d_in[4];
    const float* Whf = (const float*)d_in[5];
    const float* bhf = (const float*)d_in[6];
    const float* Wxi = (const float*)d_in[7];
    const float* bxi = (const float*)d_in[8];
    const float* Whi = (const float*)d_in[9];
    const float* bhi = (const float*)d_in[10];
    const float* Wxo = (const float*)d_in[11];
    const float* bxo = (const float*)d_in[12];
    const float* Who = (const float*)d_in[13];
    const float* bho = (const float*)d_in[14];
    const float* Wxc = (const float*)d_in[15];
    const float* bxc = (const float*)d_in[16];
    const float* Whc = (const float*)d_in[17];
    const float* bhc = (const float*)d_in[18];

    pack_all_kernel<<<PACK_BLKS, 256>>>(
        (const float4*)x, (const float4*)h,
        (const float4*)Wxf, (const float4*)Wxi, (const float4*)Wxo, (const float4*)Wxc,
        (const float4*)Whf, (const float4*)Whi, (const float4*)Who, (const float4*)Whc,
        bxf, bxi, bxo, bxc, bhf, bhi, bho, bhc);

    cudaFuncSetAttribute(lstm_gemm_kernel,
                         cudaFuncAttributeMaxDynamicSharedMemorySize, SMEM_TOTAL);
    dim3 grid(N_DIM / BN, B_DIM / BM);   // (32, 32)
    lstm_gemm_kernel<<<grid, 256, SMEM_TOTAL>>>(c, (float*)d_out);
}